// round 15
// baseline (speedup 1.0000x reference)
#include <cuda_runtime.h>
#include <cuda_fp16.h>
#include <cstdint>

// ============================================================================
// out[n,c,hw] = sum_k g[(c-k)&255] * act[n,k,hw]   (circulant inverse GEMM)
// fp16 mma.sync m16n8k16 (fp32 accum). cp.async 4-slot fp32 ring (3 deep),
// self-consistent per-thread copy->convert, 1 sync/chunk (R7 pipeline) PLUS
// liveness-masked A-blocks with STRIDE-4 m-tile assignment per warp
// (m_c = warp_m + 4t) so masked work is balanced across warps every chunk.
// CTA: 256c x 64hw, 256 threads (8 warps = 4M x 2N), 2 CTAs/SM.
// ============================================================================

__device__ __align__(16) __half aext_g[256 * 32];
__device__ uint32_t g_mask;

// ---------------------------------------------------------------------------
// Prep: g = IDFT(1/DFT(delta - padded_rolled_ricker)); fp16 circulant table
// + per-block liveness mask (27-tap forward DFT, Hermitian IDFT, ballot mask).
// ---------------------------------------------------------------------------
__global__ void prep_kernel(const float* __restrict__ filt) {
    __shared__ float f_s[27];
    __shared__ float twc[256];
    __shared__ float tws[256];
    __shared__ float gre[256];
    __shared__ float gim[256];
    __shared__ float g_s[256];

    int t = threadIdx.x;
    if (t < 27) f_s[t] = filt[t];

    float s, c;
    sincospif(-(float)t / 128.0f, &s, &c);
    twc[t] = c;
    tws[t] = s;
    __syncthreads();

    // Mhat[t] = 1 - sum_i filt[i] * tw[(t*(243+i)) & 255]
    float re = 1.0f, im = 0.0f;
#pragma unroll
    for (int i = 0; i < 27; ++i) {
        int idx = (t * (243 + i)) & 255;
        re = fmaf(-f_s[i], twc[idx], re);
        im = fmaf(-f_s[i], tws[idx], im);
    }
    float inv = 1.0f / (re * re + im * im);
    gre[t] = re * inv;
    gim[t] = -im * inv;
    __syncthreads();

    // Hermitian IDFT
    {
        float a = gre[0] + gre[128] * twc[(t * 128) & 255];
        for (int q = 1; q < 128; ++q) {
            int idx = (t * q) & 255;
            a = fmaf(2.0f * gre[q], twc[idx], a);
            a = fmaf(2.0f * gim[q], tws[idx], a);
        }
        g_s[t] = a * (1.0f / 256.0f);
    }
    __syncthreads();

    for (int kk = 0; kk < 32; ++kk)
        aext_g[t * 32 + kk] = __float2half_rn(g_s[(t - kk) & 255]);

    // Block liveness via ballot: block b covers g indices [16b-31, 16b+15].
    if (t < 32) {
        float mx = 0.0f;
        if (t < 16) {
#pragma unroll 1
            for (int d = 0; d < 47; ++d)
                mx = fmaxf(mx, fabsf(g_s[(16 * t - 31 + d) & 255]));
        }
        uint32_t m = __ballot_sync(0xFFFFFFFFu, (t < 16) && (mx > 1e-5f)) & 0xFFFFu;
        if (t == 0) g_mask = m;
    }
}

// ---------------------------------------------------------------------------
// PTX helpers (base PTX: ldmatrix/mma/cp.async are sm_80 features)
// ---------------------------------------------------------------------------
__device__ __forceinline__ uint32_t smem_u32(const void* p) {
    uint32_t a;
    asm("{ .reg .u64 t; cvta.to.shared.u64 t, %1; cvt.u32.u64 %0, t; }"
        : "=r"(a) : "l"(p));
    return a;
}
__device__ __forceinline__ void ldsm_x4(uint32_t* r, uint32_t addr) {
    asm volatile("ldmatrix.sync.aligned.m8n8.x4.shared.b16 {%0,%1,%2,%3}, [%4];"
                 : "=r"(r[0]), "=r"(r[1]), "=r"(r[2]), "=r"(r[3]) : "r"(addr));
}
__device__ __forceinline__ void ldsm_x4_t(uint32_t* r, uint32_t addr) {
    asm volatile("ldmatrix.sync.aligned.m8n8.x4.trans.shared.b16 {%0,%1,%2,%3}, [%4];"
                 : "=r"(r[0]), "=r"(r[1]), "=r"(r[2]), "=r"(r[3]) : "r"(addr));
}
__device__ __forceinline__ void mma16816(float* d, const uint32_t* a,
                                         const uint32_t* b) {
    asm volatile(
        "mma.sync.aligned.m16n8k16.row.col.f32.f16.f16.f32 "
        "{%0,%1,%2,%3},{%4,%5,%6,%7},{%8,%9},{%0,%1,%2,%3};"
        : "+f"(d[0]), "+f"(d[1]), "+f"(d[2]), "+f"(d[3])
        : "r"(a[0]), "r"(a[1]), "r"(a[2]), "r"(a[3]), "r"(b[0]), "r"(b[1]));
}
__device__ __forceinline__ void cp_async16(uint32_t dst, const void* src) {
    asm volatile("cp.async.cg.shared.global [%0], [%1], 16;"
                 :: "r"(dst), "l"(src) : "memory");
}
__device__ __forceinline__ void cp_commit() {
    asm volatile("cp.async.commit_group;" ::: "memory");
}
template <int N>
__device__ __forceinline__ void cp_wait() {
    asm volatile("cp.async.wait_group %0;" :: "n"(N) : "memory");
}

// SMEM layout
static constexpr uint32_t A_PITCH = 80;    // 32 fp16 (64B) + 16B pad
static constexpr uint32_t S_PITCH = 272;   // 64 fp32 (256B) + 16B pad
static constexpr uint32_t B_PITCH = 144;   // 64 fp16 (128B) + 16B pad
static constexpr uint32_t OFF_A   = 0;                  // 256*80 = 20480
static constexpr uint32_t OFF_S   = 20480;              // fp32 ring, 4 slots
static constexpr uint32_t S_SLOT  = 32 * S_PITCH;       // 8704
static constexpr uint32_t OFF_B   = 20480 + 4 * S_SLOT; // 55296, fp16 x2
static constexpr uint32_t B_BUF   = 32 * B_PITCH;       // 4608
static constexpr uint32_t SMEM_BYTES = OFF_B + 2 * B_BUF;  // 64512

__global__ __launch_bounds__(256, 2)
void mma_toeplitz_kernel(const float* __restrict__ act, float* __restrict__ out) {
    extern __shared__ __align__(128) char smem[];
    const uint32_t sb = smem_u32(smem);
    const int tid = threadIdx.x;
    const int lid = tid & 31;
    const int wid = tid >> 5;
    const int warp_m = wid >> 1;   // 0..3; m-tiles at blocks warp_m + 4t
    const int warp_n = wid & 1;    // 0..1 -> 32 hw each
    const int hw0 = blockIdx.x * 64;
    const int n   = blockIdx.y;

    const float* actn = act + (size_t)n * (256 * 4096);
    float*       outn = out + (size_t)n * (256 * 4096);

    const uint32_t mask = g_mask;

    // Copy circulant A table gmem -> smem (64B rows -> pitch 80)
    {
        const float4* src = (const float4*)aext_g;
#pragma unroll
        for (int l = 0; l < 4; ++l) {
            int i = tid + l * 256;
            uint32_t dst = (uint32_t)(i >> 2) * A_PITCH + (uint32_t)(i & 3) * 16;
            *(float4*)(smem + OFF_A + dst) = src[i];
        }
    }

    // Per-thread copy/convert coordinates (self-consistent: each thread
    // cp.asyncs exactly the 32 bytes it later converts).
    const int cr = tid >> 3;                         // k row 0..31
    const int cc = tid & 7;                          // 16B col 0..7
    const uint32_t ring_rd = (uint32_t)cr * S_PITCH + (uint32_t)cc * 16;
    const uint32_t sts_off = (uint32_t)cr * B_PITCH + (uint32_t)cc * 8;
    const float* gsrc = &actn[(size_t)cr * 4096 + hw0 + cc * 4];

#define CP_CHUNK(q)                                                          \
    do {                                                                     \
        uint32_t d0 = sb + OFF_S + (uint32_t)((q) & 3) * S_SLOT + ring_rd;   \
        const float* s0 = gsrc + (size_t)(q) * 32 * 4096;                    \
        cp_async16(d0, s0);                                                  \
        cp_async16(d0 + 128, s0 + 32);                                       \
        cp_commit();                                                         \
    } while (0)

#define CVT_CHUNK(q)                                                         \
    do {                                                                     \
        const char* slot = smem + OFF_S + (uint32_t)((q) & 3) * S_SLOT;      \
        float4 va = *(const float4*)(slot + ring_rd);                        \
        float4 vb = *(const float4*)(slot + ring_rd + 128);                  \
        char* bdst = smem + OFF_B + (uint32_t)((q) & 1) * B_BUF;             \
        __half2 a0 = __floats2half2_rn(va.x, va.y);                          \
        __half2 a1 = __floats2half2_rn(va.z, va.w);                          \
        __half2 b0 = __floats2half2_rn(vb.x, vb.y);                          \
        __half2 b1 = __floats2half2_rn(vb.z, vb.w);                          \
        *(uint2*)(bdst + sts_off) =                                          \
            make_uint2(*(uint32_t*)&a0, *(uint32_t*)&a1);                    \
        *(uint2*)(bdst + sts_off + 64) =                                     \
            make_uint2(*(uint32_t*)&b0, *(uint32_t*)&b1);                    \
    } while (0)

    // Prologue: 3 chunks in flight, chunk 0 converted.
    CP_CHUNK(0);
    CP_CHUNK(1);
    CP_CHUNK(2);
    cp_wait<2>();
    CVT_CHUNK(0);

    float acc[4][4][4] = {};

#pragma unroll
    for (int j = 0; j < 8; ++j) {
        __syncthreads();  // fp16 buf(j&1) published; prev reads of buf done

        if (j + 3 < 8) CP_CHUNK(j + 3);

        // Stride-4 m-tiles: block index (warp_m + 4*mt); alive bits balanced.
        int al[4];
#pragma unroll
        for (int mt = 0; mt < 4; ++mt)
            al[mt] = (mask >> ((warp_m + 4 * mt + 32 - 2 * j) & 15)) & 1;

        const uint32_t bbase = sb + OFF_B + (uint32_t)(j & 1) * B_BUF;
#pragma unroll
        for (int step = 0; step < 2; ++step) {
            uint32_t brow = (uint32_t)(step * 16 + (lid & 15));
            uint32_t Bf[2][4];
#pragma unroll
            for (int bh = 0; bh < 2; ++bh) {
                uint32_t bcol = (uint32_t)(warp_n * 32 + bh * 16 + ((lid >> 4) << 3));
                ldsm_x4_t(Bf[bh], bbase + brow * B_PITCH + bcol * 2);
            }
#pragma unroll
            for (int mt = 0; mt < 4; ++mt) {
                if (!al[mt]) continue;
                int sbase = ((warp_m + 4 * mt) * 16 - j * 32) & 255;
                uint32_t arow = (uint32_t)(sbase + (lid & 15));
                uint32_t acol = (uint32_t)(step * 32 + ((lid >> 4) << 4));
                uint32_t Af[4];
                ldsm_x4(Af, sb + OFF_A + arow * A_PITCH + acol);
                mma16816(acc[mt][0], Af, Bf[0]);
                mma16816(acc[mt][1], Af, Bf[0] + 2);
                mma16816(acc[mt][2], Af, Bf[1]);
                mma16816(acc[mt][3], Af, Bf[1] + 2);
            }
        }

        // Convert chunk j+1 into the other fp16 buffer (own bytes only).
        if (j < 7) {
            if (j < 5)       cp_wait<2>();
            else if (j == 5) cp_wait<1>();
            else             cp_wait<0>();
            CVT_CHUNK(j + 1);
        }
    }
#undef CP_CHUNK
#undef CVT_CHUNK

    // Epilogue: direct stores (lane quads cover 32B sectors)
#pragma unroll
    for (int mt = 0; mt < 4; ++mt) {
        int c = (warp_m + 4 * mt) * 16 + (lid >> 2);
#pragma unroll
        for (int nq = 0; nq < 4; ++nq) {
            int col = hw0 + warp_n * 32 + nq * 8 + (lid & 3) * 2;
            *(float2*)&outn[(size_t)c * 4096 + col] =
                make_float2(acc[mt][nq][0], acc[mt][nq][1]);
            *(float2*)&outn[(size_t)(c + 8) * 4096 + col] =
                make_float2(acc[mt][nq][2], acc[mt][nq][3]);
        }
    }
}

// ---------------------------------------------------------------------------
extern "C" void kernel_launch(void* const* d_in, const int* in_sizes, int n_in,
                              void* d_out, int out_size) {
    const float* act;
    const float* filt;
    if (n_in >= 2 && in_sizes[0] == 27) {
        filt = (const float*)d_in[0];
        act  = (const float*)d_in[1];
    } else {
        act  = (const float*)d_in[0];
        filt = (const float*)d_in[1];
    }

    cudaFuncSetAttribute(mma_toeplitz_kernel,
                         cudaFuncAttributeMaxDynamicSharedMemorySize, SMEM_BYTES);

    prep_kernel<<<1, 256>>>(filt);

    dim3 grid(4096 / 64, 32);   // (64, 32) = 2048 CTAs
    mma_toeplitz_kernel<<<grid, 256, SMEM_BYTES>>>(act, (float*)d_out);
}

// round 16
// speedup vs baseline: 1.0364x; 1.0364x over previous
#include <cuda_runtime.h>
#include <cuda_fp16.h>
#include <cstdint>

// ============================================================================
// out[n,c,hw] = sum_k g[(c-k)&255] * act[n,k,hw]   (circulant inverse GEMM)
// fp16 mma.sync m16n8k16 (fp32 accum). Liveness-masked A-blocks; all 8 B
// chunks staged up front; barrier-free compute; EARLY per-mt stores (tile
// stored right after its last alive chunk -> writes overlap compute).
// CTA: 256c x 64hw, 256 threads (8 warps = 4M x 2N), 2 CTAs/SM.
// Prep kernel: 27-tap forward DFT + Hermitian IDFT + ballot mask (~1-2us).
// ============================================================================

__device__ __align__(16) __half aext_g[256 * 32];
__device__ uint32_t g_mask;

// ---------------------------------------------------------------------------
// Prep: g = IDFT(1/DFT(delta - padded_rolled_ricker)); fp16 circulant table
// + per-block liveness mask.
// ---------------------------------------------------------------------------
__global__ void prep_kernel(const float* __restrict__ filt) {
    __shared__ float f_s[27];
    __shared__ float twc[256];
    __shared__ float tws[256];
    __shared__ float gre[256];
    __shared__ float gim[256];
    __shared__ float g_s[256];

    int t = threadIdx.x;
    if (t < 27) f_s[t] = filt[t];

    float s, c;
    sincospif(-(float)t / 128.0f, &s, &c);
    twc[t] = c;
    tws[t] = s;
    __syncthreads();

    // Mhat[t] = 1 - sum_i filt[i] * tw[(t*(243+i)) & 255]
    float re = 1.0f, im = 0.0f;
#pragma unroll
    for (int i = 0; i < 27; ++i) {
        int idx = (t * (243 + i)) & 255;
        re = fmaf(-f_s[i], twc[idx], re);
        im = fmaf(-f_s[i], tws[idx], im);
    }
    float inv = 1.0f / (re * re + im * im);
    gre[t] = re * inv;
    gim[t] = -im * inv;
    __syncthreads();

    // Hermitian IDFT
    {
        float a = gre[0] + gre[128] * twc[(t * 128) & 255];
        for (int q = 1; q < 128; ++q) {
            int idx = (t * q) & 255;
            a = fmaf(2.0f * gre[q], twc[idx], a);
            a = fmaf(2.0f * gim[q], tws[idx], a);
        }
        g_s[t] = a * (1.0f / 256.0f);
    }
    __syncthreads();

    for (int kk = 0; kk < 32; ++kk)
        aext_g[t * 32 + kk] = __float2half_rn(g_s[(t - kk) & 255]);

    // Block liveness via ballot: block b covers g indices [16b-31, 16b+15].
    if (t < 32) {
        float mx = 0.0f;
        if (t < 16) {
#pragma unroll 1
            for (int d = 0; d < 47; ++d)
                mx = fmaxf(mx, fabsf(g_s[(16 * t - 31 + d) & 255]));
        }
        uint32_t m = __ballot_sync(0xFFFFFFFFu, (t < 16) && (mx > 1e-5f)) & 0xFFFFu;
        if (t == 0) g_mask = m;
    }
}

// ---------------------------------------------------------------------------
// PTX helpers (base PTX: ldmatrix + mma.sync, sm_80 features)
// ---------------------------------------------------------------------------
__device__ __forceinline__ uint32_t smem_u32(const void* p) {
    uint32_t a;
    asm("{ .reg .u64 t; cvta.to.shared.u64 t, %1; cvt.u32.u64 %0, t; }"
        : "=r"(a) : "l"(p));
    return a;
}
__device__ __forceinline__ void ldsm_x4(uint32_t* r, uint32_t addr) {
    asm volatile("ldmatrix.sync.aligned.m8n8.x4.shared.b16 {%0,%1,%2,%3}, [%4];"
                 : "=r"(r[0]), "=r"(r[1]), "=r"(r[2]), "=r"(r[3]) : "r"(addr));
}
__device__ __forceinline__ void ldsm_x4_t(uint32_t* r, uint32_t addr) {
    asm volatile("ldmatrix.sync.aligned.m8n8.x4.trans.shared.b16 {%0,%1,%2,%3}, [%4];"
                 : "=r"(r[0]), "=r"(r[1]), "=r"(r[2]), "=r"(r[3]) : "r"(addr));
}
__device__ __forceinline__ void mma16816(float* d, const uint32_t* a,
                                         const uint32_t* b) {
    asm volatile(
        "mma.sync.aligned.m16n8k16.row.col.f32.f16.f16.f32 "
        "{%0,%1,%2,%3},{%4,%5,%6,%7},{%8,%9},{%0,%1,%2,%3};"
        : "+f"(d[0]), "+f"(d[1]), "+f"(d[2]), "+f"(d[3])
        : "r"(a[0]), "r"(a[1]), "r"(a[2]), "r"(a[3]), "r"(b[0]), "r"(b[1]));
}

// SMEM layout
static constexpr uint32_t A_PITCH = 80;    // 32 fp16 (64B) + 16B pad
static constexpr uint32_t B_PITCH = 144;   // 64 fp16 (128B) + 16B pad
static constexpr uint32_t OFF_A   = 0;                  // 256*80 = 20480
static constexpr uint32_t OFF_B   = 20480;              // 8 chunk buffers
static constexpr uint32_t B_BUF   = 32 * B_PITCH;       // 4608
static constexpr uint32_t SMEM_BYTES = 20480 + 8 * B_BUF;  // 57344

__global__ __launch_bounds__(256, 2)
void mma_toeplitz_kernel(const float* __restrict__ act, float* __restrict__ out) {
    extern __shared__ __align__(128) char smem[];
    const uint32_t sb = smem_u32(smem);
    const int tid = threadIdx.x;
    const int lid = tid & 31;
    const int wid = tid >> 5;
    const int warp_m = wid >> 1;   // 0..3 -> 64 c each
    const int warp_n = wid & 1;    // 0..1 -> 32 hw each
    const int hw0 = blockIdx.x * 64;
    const int n   = blockIdx.y;

    const float* actn = act + (size_t)n * (256 * 4096);
    float*       outn = out + (size_t)n * (256 * 4096);

    const uint32_t mask = g_mask;

    // Per-mt last alive chunk (early-store point; 0 if tile fully dead)
    int last_j[4];
#pragma unroll
    for (int mt = 0; mt < 4; ++mt) {
        last_j[mt] = 0;
#pragma unroll
        for (int j = 0; j < 8; ++j)
            if ((mask >> ((warp_m * 4 + mt + 32 - 2 * j) & 15)) & 1) last_j[mt] = j;
    }

    // Copy circulant A table gmem -> smem (64B rows -> pitch 80)
    {
        const float4* src = (const float4*)aext_g;
#pragma unroll
        for (int l = 0; l < 4; ++l) {
            int i = tid + l * 256;
            uint32_t dst = (uint32_t)(i >> 2) * A_PITCH + (uint32_t)(i & 3) * 16;
            *(float4*)(smem + OFF_A + dst) = src[i];
        }
    }

    // ---- Stage ALL 8 chunks: LDG fp32 -> cvt -> STS fp16 -----------------
    {
        const int cr = tid >> 3;          // 0..31
        const int cc = tid & 7;           // 0..7
        const float* gsrc = &actn[(size_t)cr * 4096 + hw0 + cc * 8];
        const uint32_t sts = sb + OFF_B + (uint32_t)cr * B_PITCH + (uint32_t)cc * 16;
#pragma unroll
        for (int q = 0; q < 8; q += 2) {
            float4 a0 = *(const float4*)(gsrc + (size_t)q * 32 * 4096);
            float4 a1 = *(const float4*)(gsrc + (size_t)q * 32 * 4096 + 4);
            float4 b0 = *(const float4*)(gsrc + (size_t)(q + 1) * 32 * 4096);
            float4 b1 = *(const float4*)(gsrc + (size_t)(q + 1) * 32 * 4096 + 4);
            __half2 h0 = __floats2half2_rn(a0.x, a0.y);
            __half2 h1 = __floats2half2_rn(a0.z, a0.w);
            __half2 h2 = __floats2half2_rn(a1.x, a1.y);
            __half2 h3 = __floats2half2_rn(a1.z, a1.w);
            asm volatile("st.shared.v4.b32 [%0], {%1,%2,%3,%4};"
                         :: "r"(sts + (uint32_t)q * B_BUF),
                            "r"(*(uint32_t*)&h0), "r"(*(uint32_t*)&h1),
                            "r"(*(uint32_t*)&h2), "r"(*(uint32_t*)&h3) : "memory");
            __half2 g0 = __floats2half2_rn(b0.x, b0.y);
            __half2 g1 = __floats2half2_rn(b0.z, b0.w);
            __half2 g2 = __floats2half2_rn(b1.x, b1.y);
            __half2 g3 = __floats2half2_rn(b1.z, b1.w);
            asm volatile("st.shared.v4.b32 [%0], {%1,%2,%3,%4};"
                         :: "r"(sts + (uint32_t)(q + 1) * B_BUF),
                            "r"(*(uint32_t*)&g0), "r"(*(uint32_t*)&g1),
                            "r"(*(uint32_t*)&g2), "r"(*(uint32_t*)&g3) : "memory");
        }
    }
    __syncthreads();   // A table + all B chunks visible

    // ---- Barrier-free compute + early per-mt stores ------------------------
    float acc[4][4][4] = {};

#pragma unroll
    for (int j = 0; j < 8; ++j) {
        int al[4];
        int any = 0;
#pragma unroll
        for (int mt = 0; mt < 4; ++mt) {
            al[mt] = (mask >> ((warp_m * 4 + mt + 32 - 2 * j) & 15)) & 1;
            any |= al[mt];
        }

        if (any) {
            const uint32_t bbase = sb + OFF_B + (uint32_t)j * B_BUF;
#pragma unroll
            for (int step = 0; step < 2; ++step) {
                uint32_t brow = (uint32_t)(step * 16 + (lid & 15));
                uint32_t Bf[2][4];
#pragma unroll
                for (int bh = 0; bh < 2; ++bh) {
                    uint32_t bcol = (uint32_t)(warp_n * 32 + bh * 16 + ((lid >> 4) << 3));
                    ldsm_x4_t(Bf[bh], bbase + brow * B_PITCH + bcol * 2);
                }
#pragma unroll
                for (int mt = 0; mt < 4; ++mt) {
                    if (!al[mt]) continue;
                    int sbase = ((warp_m * 64 + mt * 16) - j * 32) & 255;
                    uint32_t arow = (uint32_t)(sbase + (lid & 15));
                    uint32_t acol = (uint32_t)(step * 32 + ((lid >> 4) << 4));
                    uint32_t Af[4];
                    ldsm_x4(Af, sb + OFF_A + arow * A_PITCH + acol);
                    mma16816(acc[mt][0], Af, Bf[0]);
                    mma16816(acc[mt][1], Af, Bf[0] + 2);
                    mma16816(acc[mt][2], Af, Bf[1]);
                    mma16816(acc[mt][3], Af, Bf[1] + 2);
                }
            }
        }

        // Early stores: tiles whose final alive chunk was j are complete.
#pragma unroll
        for (int mt = 0; mt < 4; ++mt) {
            if (last_j[mt] != j) continue;
            int c = warp_m * 64 + mt * 16 + (lid >> 2);
#pragma unroll
            for (int nq = 0; nq < 4; ++nq) {
                int col = hw0 + warp_n * 32 + nq * 8 + (lid & 3) * 2;
                *(float2*)&outn[(size_t)c * 4096 + col] =
                    make_float2(acc[mt][nq][0], acc[mt][nq][1]);
                *(float2*)&outn[(size_t)(c + 8) * 4096 + col] =
                    make_float2(acc[mt][nq][2], acc[mt][nq][3]);
            }
        }
    }
}

// ---------------------------------------------------------------------------
extern "C" void kernel_launch(void* const* d_in, const int* in_sizes, int n_in,
                              void* d_out, int out_size) {
    const float* act;
    const float* filt;
    if (n_in >= 2 && in_sizes[0] == 27) {
        filt = (const float*)d_in[0];
        act  = (const float*)d_in[1];
    } else {
        act  = (const float*)d_in[0];
        filt = (const float*)d_in[1];
    }

    cudaFuncSetAttribute(mma_toeplitz_kernel,
                         cudaFuncAttributeMaxDynamicSharedMemorySize, SMEM_BYTES);

    prep_kernel<<<1, 256>>>(filt);

    dim3 grid(4096 / 64, 32);   // (64, 32) = 2048 CTAs
    mma_toeplitz_kernel<<<grid, 256, SMEM_BYTES>>>(act, (float*)d_out);
}

// round 17
// speedup vs baseline: 1.0918x; 1.0534x over previous
#include <cuda_runtime.h>
#include <cuda_fp16.h>
#include <cstdint>

// ============================================================================
// out[n,c,hw] = sum_k g[(c-k)&255] * act[n,k,hw]   (circulant inverse GEMM)
// fp16 mma.sync m16n8k16 (fp32 accum). g has narrow effective support, so
// 16c x 32k A-blocks with max|g| < 1e-5 are skipped (runtime 16-bit mask).
// Staging: ALL 16 LDG.128 issued up front (max MLP; acc regs not yet live),
// A-table copy hidden under the load shadow, then cvt->STS all 8 chunks,
// ONE __syncthreads, barrier-free masked compute, direct epilogue stores.
// CTA: 256c x 64hw, 256 threads (8 warps = 4M x 2N), 2 CTAs/SM.
// ============================================================================

__device__ __align__(16) __half aext_g[256 * 32];
__device__ uint32_t g_mask;

// ---------------------------------------------------------------------------
// Prep: g = IDFT(1/DFT(delta - padded_rolled_ricker)); fp16 circulant table
// + per-block liveness mask (27-tap forward DFT, Hermitian IDFT, ballot mask).
// ---------------------------------------------------------------------------
__global__ void prep_kernel(const float* __restrict__ filt) {
    __shared__ float f_s[27];
    __shared__ float twc[256];
    __shared__ float tws[256];
    __shared__ float gre[256];
    __shared__ float gim[256];
    __shared__ float g_s[256];

    int t = threadIdx.x;
    if (t < 27) f_s[t] = filt[t];

    float s, c;
    sincospif(-(float)t / 128.0f, &s, &c);
    twc[t] = c;
    tws[t] = s;
    __syncthreads();

    // Mhat[t] = 1 - sum_i filt[i] * tw[(t*(243+i)) & 255]
    float re = 1.0f, im = 0.0f;
#pragma unroll
    for (int i = 0; i < 27; ++i) {
        int idx = (t * (243 + i)) & 255;
        re = fmaf(-f_s[i], twc[idx], re);
        im = fmaf(-f_s[i], tws[idx], im);
    }
    float inv = 1.0f / (re * re + im * im);
    gre[t] = re * inv;
    gim[t] = -im * inv;
    __syncthreads();

    // Hermitian IDFT
    {
        float a = gre[0] + gre[128] * twc[(t * 128) & 255];
        for (int q = 1; q < 128; ++q) {
            int idx = (t * q) & 255;
            a = fmaf(2.0f * gre[q], twc[idx], a);
            a = fmaf(2.0f * gim[q], tws[idx], a);
        }
        g_s[t] = a * (1.0f / 256.0f);
    }
    __syncthreads();

    for (int kk = 0; kk < 32; ++kk)
        aext_g[t * 32 + kk] = __float2half_rn(g_s[(t - kk) & 255]);

    // Block liveness via ballot: block b covers g indices [16b-31, 16b+15].
    if (t < 32) {
        float mx = 0.0f;
        if (t < 16) {
#pragma unroll 1
            for (int d = 0; d < 47; ++d)
                mx = fmaxf(mx, fabsf(g_s[(16 * t - 31 + d) & 255]));
        }
        uint32_t m = __ballot_sync(0xFFFFFFFFu, (t < 16) && (mx > 1e-5f)) & 0xFFFFu;
        if (t == 0) g_mask = m;
    }
}

// ---------------------------------------------------------------------------
// PTX helpers (base PTX: ldmatrix + mma.sync, sm_80 features)
// ---------------------------------------------------------------------------
__device__ __forceinline__ uint32_t smem_u32(const void* p) {
    uint32_t a;
    asm("{ .reg .u64 t; cvta.to.shared.u64 t, %1; cvt.u32.u64 %0, t; }"
        : "=r"(a) : "l"(p));
    return a;
}
__device__ __forceinline__ void ldsm_x4(uint32_t* r, uint32_t addr) {
    asm volatile("ldmatrix.sync.aligned.m8n8.x4.shared.b16 {%0,%1,%2,%3}, [%4];"
                 : "=r"(r[0]), "=r"(r[1]), "=r"(r[2]), "=r"(r[3]) : "r"(addr));
}
__device__ __forceinline__ void ldsm_x4_t(uint32_t* r, uint32_t addr) {
    asm volatile("ldmatrix.sync.aligned.m8n8.x4.trans.shared.b16 {%0,%1,%2,%3}, [%4];"
                 : "=r"(r[0]), "=r"(r[1]), "=r"(r[2]), "=r"(r[3]) : "r"(addr));
}
__device__ __forceinline__ void mma16816(float* d, const uint32_t* a,
                                         const uint32_t* b) {
    asm volatile(
        "mma.sync.aligned.m16n8k16.row.col.f32.f16.f16.f32 "
        "{%0,%1,%2,%3},{%4,%5,%6,%7},{%8,%9},{%0,%1,%2,%3};"
        : "+f"(d[0]), "+f"(d[1]), "+f"(d[2]), "+f"(d[3])
        : "r"(a[0]), "r"(a[1]), "r"(a[2]), "r"(a[3]), "r"(b[0]), "r"(b[1]));
}

// SMEM layout
static constexpr uint32_t A_PITCH = 80;    // 32 fp16 (64B) + 16B pad
static constexpr uint32_t B_PITCH = 144;   // 64 fp16 (128B) + 16B pad
static constexpr uint32_t OFF_A   = 0;                  // 256*80 = 20480
static constexpr uint32_t OFF_B   = 20480;              // 8 chunk buffers
static constexpr uint32_t B_BUF   = 32 * B_PITCH;       // 4608
static constexpr uint32_t SMEM_BYTES = 20480 + 8 * B_BUF;  // 57344

__global__ __launch_bounds__(256, 2)
void mma_toeplitz_kernel(const float* __restrict__ act, float* __restrict__ out) {
    extern __shared__ __align__(128) char smem[];
    const uint32_t sb = smem_u32(smem);
    const int tid = threadIdx.x;
    const int lid = tid & 31;
    const int wid = tid >> 5;
    const int warp_m = wid >> 1;   // 0..3 -> 64 c each
    const int warp_n = wid & 1;    // 0..1 -> 32 hw each
    const int hw0 = blockIdx.x * 64;
    const int n   = blockIdx.y;

    const float* actn = act + (size_t)n * (256 * 4096);
    float*       outn = out + (size_t)n * (256 * 4096);

    const uint32_t mask = g_mask;

    // ---- Stage: issue ALL 16 LDG.128 first (acc regs not yet live) --------
    const int cr = tid >> 3;          // k row 0..31
    const int cc = tid & 7;           // 8-float col 0..7
    const float* gsrc = &actn[(size_t)cr * 4096 + hw0 + cc * 8];
    float4 v0[8], v1[8];
#pragma unroll
    for (int q = 0; q < 8; ++q) {
        v0[q] = *(const float4*)(gsrc + (size_t)q * 32 * 4096);
        v1[q] = *(const float4*)(gsrc + (size_t)q * 32 * 4096 + 4);
    }

    // A-table copy (L2-hit) hides under the staging-load shadow
    {
        const float4* src = (const float4*)aext_g;
#pragma unroll
        for (int l = 0; l < 4; ++l) {
            int i = tid + l * 256;
            uint32_t dst = (uint32_t)(i >> 2) * A_PITCH + (uint32_t)(i & 3) * 16;
            *(float4*)(smem + OFF_A + dst) = src[i];
        }
    }

    // cvt fp32 -> fp16, STS all 8 chunks
    {
        const uint32_t sts = sb + OFF_B + (uint32_t)cr * B_PITCH + (uint32_t)cc * 16;
#pragma unroll
        for (int q = 0; q < 8; ++q) {
            __half2 h0 = __floats2half2_rn(v0[q].x, v0[q].y);
            __half2 h1 = __floats2half2_rn(v0[q].z, v0[q].w);
            __half2 h2 = __floats2half2_rn(v1[q].x, v1[q].y);
            __half2 h3 = __floats2half2_rn(v1[q].z, v1[q].w);
            asm volatile("st.shared.v4.b32 [%0], {%1,%2,%3,%4};"
                         :: "r"(sts + (uint32_t)q * B_BUF),
                            "r"(*(uint32_t*)&h0), "r"(*(uint32_t*)&h1),
                            "r"(*(uint32_t*)&h2), "r"(*(uint32_t*)&h3) : "memory");
        }
    }
    __syncthreads();   // A table + all B chunks visible

    // ---- Barrier-free compute: skip dead A blocks --------------------------
    float acc[4][4][4] = {};

#pragma unroll
    for (int j = 0; j < 8; ++j) {
        int al[4];
        int any = 0;
#pragma unroll
        for (int mt = 0; mt < 4; ++mt) {
            al[mt] = (mask >> ((warp_m * 4 + mt + 32 - 2 * j) & 15)) & 1;
            any |= al[mt];
        }
        if (!any) continue;

        const uint32_t bbase = sb + OFF_B + (uint32_t)j * B_BUF;
#pragma unroll
        for (int step = 0; step < 2; ++step) {
            uint32_t brow = (uint32_t)(step * 16 + (lid & 15));
            uint32_t Bf[2][4];
#pragma unroll
            for (int bh = 0; bh < 2; ++bh) {
                uint32_t bcol = (uint32_t)(warp_n * 32 + bh * 16 + ((lid >> 4) << 3));
                ldsm_x4_t(Bf[bh], bbase + brow * B_PITCH + bcol * 2);
            }
#pragma unroll
            for (int mt = 0; mt < 4; ++mt) {
                if (!al[mt]) continue;
                int sbase = ((warp_m * 64 + mt * 16) - j * 32) & 255;
                uint32_t arow = (uint32_t)(sbase + (lid & 15));
                uint32_t acol = (uint32_t)(step * 32 + ((lid >> 4) << 4));
                uint32_t Af[4];
                ldsm_x4(Af, sb + OFF_A + arow * A_PITCH + acol);
                mma16816(acc[mt][0], Af, Bf[0]);
                mma16816(acc[mt][1], Af, Bf[0] + 2);
                mma16816(acc[mt][2], Af, Bf[1]);
                mma16816(acc[mt][3], Af, Bf[1] + 2);
            }
        }
    }

    // Epilogue: direct stores (lane quads cover 32B sectors)
#pragma unroll
    for (int mt = 0; mt < 4; ++mt) {
        int c = warp_m * 64 + mt * 16 + (lid >> 2);
#pragma unroll
        for (int nq = 0; nq < 4; ++nq) {
            int col = hw0 + warp_n * 32 + nq * 8 + (lid & 3) * 2;
            *(float2*)&outn[(size_t)c * 4096 + col] =
                make_float2(acc[mt][nq][0], acc[mt][nq][1]);
            *(float2*)&outn[(size_t)(c + 8) * 4096 + col] =
                make_float2(acc[mt][nq][2], acc[mt][nq][3]);
        }
    }
}

// ---------------------------------------------------------------------------
extern "C" void kernel_launch(void* const* d_in, const int* in_sizes, int n_in,
                              void* d_out, int out_size) {
    const float* act;
    const float* filt;
    if (n_in >= 2 && in_sizes[0] == 27) {
        filt = (const float*)d_in[0];
        act  = (const float*)d_in[1];
    } else {
        act  = (const float*)d_in[0];
        filt = (const float*)d_in[1];
    }

    cudaFuncSetAttribute(mma_toeplitz_kernel,
                         cudaFuncAttributeMaxDynamicSharedMemorySize, SMEM_BYTES);

    prep_kernel<<<1, 256>>>(filt);

    dim3 grid(4096 / 64, 32);   // (64, 32) = 2048 CTAs
    mma_toeplitz_kernel<<<grid, 256, SMEM_BYTES>>>(act, (float*)d_out);
}